// round 15
// baseline (speedup 1.0000x reference)
#include <cuda_runtime.h>
#include <cuda_fp16.h>
#include <cstdint>
#include <math.h>

#define BATCH 256
#define HDIM  128
#define NTOK  511
#define NARITY 255
#define AZROWS 65280   // sum over levels 0..7 of 256*2^l

// ---------------------------------------------------------------------------
// Static device scratch (allocation-free rule):
//   Bc   : combined transposed weights [13 gates][n=128][k=256] fp16
//   Aleaf: leaf embeddings [65536][128] fp16
//   Az   : ALL levels' inputs [65280 rows][384 k] fp16, level l at row
//          off(l) = 256*(256 - 2^(l+1))  (x 0..127 | h_l 128..255 | h_r 256..383)
//   gbuf : gate pre-activations for ALL levels [65280][13*128] fp16
//   cbuf : cell-state ping-pong [2][65536][128] fp32
//   list/cnt : per-level arity-compacted LOCAL row lists (0=binary, 1=unary)
// ---------------------------------------------------------------------------
__device__ __align__(16) __half g_Bc[13 * 128 * 256];
__device__ __align__(16) __half g_Aleaf[65536 * 128];
__device__ __align__(16) __half g_Az[AZROWS * 384];
__device__ __align__(16) __half g_gbuf[(size_t)AZROWS * 1664];
__device__ __align__(16) float  g_cbuf[2][65536 * 128];
__device__ int g_list[8][2][32768];
__device__ int g_cnt[8][2];

__device__ __forceinline__ float sigmoid_(float x) { return 1.0f / (1.0f + expf(-x)); }
__device__ __forceinline__ float tanh_(float x)    { return 1.0f - 2.0f / (expf(2.0f * x) + 1.0f); }

__device__ __forceinline__ void cp16(uint32_t dst, const void* src) {
    asm volatile("cp.async.ca.shared.global [%0], [%1], 16;" :: "r"(dst), "l"(src));
}

// ---------------------------------------------------------------------------
// prep_B: weights -> fp16 combined-B; zeroes the per-level counters.
// ---------------------------------------------------------------------------
__global__ void prep_B_kernel(const float* __restrict__ W,
                              const float* __restrict__ Ubin,
                              const float* __restrict__ Uun)
{
    const int idx = blockIdx.x * 256 + threadIdx.x;
    if (idx < 16) ((int*)g_cnt)[idx] = 0;
    if (idx >= 13 * 128 * 256) return;
    const int g = idx >> 15;
    const int n = (idx >> 8) & 127;
    const int k = idx & 255;
    float v;
    if (g < 4)       v = (k < 128) ? W[g * 16384 + k * 128 + n] : 0.f;
    else if (g < 9)  v = Ubin[(g - 4) * 32768 + k * 128 + n];
    else             v = (k < 128) ? Uun[(g - 9) * 16384 + k * 128 + n] : 0.f;
    g_Bc[idx] = __float2half_rn(v);
}

__global__ void stage_leaf_kernel(const int* __restrict__ tokens,
                                  const float* __restrict__ emb)
{
    const int idx = blockIdx.x * 256 + threadIdx.x;
    const int row = idx >> 7;
    const int col = idx & 127;
    const int b = row >> 8, n = row & 255;
    const int tok = __ldg(&tokens[b * NTOK + 255 + n]);
    g_Aleaf[idx] = __float2half_rn(__ldg(&emb[(size_t)tok * 128 + col]));
}

// Decode global Az row -> (level, level base offset).
__device__ __forceinline__ void az_decode(int grow, int& l, int& off)
{
    const int u = AZROWS - grow;
    const int w = (u - 1) >> 8;
    l = 31 - __clz(w + 1);
    off = 256 * (256 - (2 << l));
}

__global__ void stage_x_all_kernel(const int* __restrict__ tokens,
                                   const float* __restrict__ emb)
{
    const int idx = blockIdx.x * 256 + threadIdx.x;
    const int grow = idx >> 7;
    const int col  = idx & 127;
    int l, off;
    az_decode(grow, l, off);
    const int local = grow - off;
    const int b = local >> l;
    const int n = local - (b << l);
    const int tok = __ldg(&tokens[b * NTOK + ((1 << l) - 1) + n]);
    g_Az[(size_t)grow * 384 + col] =
        __float2half_rn(__ldg(&emb[(size_t)tok * 128 + col]));
}

// Classify all levels' nodes; warp-aggregated atomics (warps are level-uniform
// because level boundaries are multiples of 256 rows).
__global__ void classify_all_kernel(const int* __restrict__ arity)
{
    const int grow = blockIdx.x * 256 + threadIdx.x;  // exact cover of AZROWS
    const int lane = threadIdx.x & 31;
    int l, off;
    az_decode(grow, l, off);
    const int local = grow - off;
    const int b = local >> l;
    const int n = local - (b << l);
    const int ar = __ldg(&arity[b * NARITY + ((1 << l) - 1) + n]);
    const int w = (ar == 1) ? 0 : 1;
    const unsigned m0 = __ballot_sync(0xffffffffu, w == 0);
    const unsigned mym = w ? ~m0 : m0;
    const int rank   = __popc(mym & ((1u << lane) - 1u));
    const int leader = __ffs(mym) - 1;
    int base = 0;
    if (lane == leader) base = atomicAdd(&g_cnt[l][w], __popc(mym));
    base = __shfl_sync(0xffffffffu, base, leader);
    g_list[l][w][base + rank] = local;
}

// ---------------------------------------------------------------------------
// Upfront GEMMs (mma.sync m16n8k16 fp16, 128x128 tile, 8 warps 2(M)x4(N),
// KC=32, cp.async double-buffered).
//   mode 2: Wx gates (slots 0..3) DENSE over ALL levels' rows
//           (blockIdx.x = slot, blockIdx.y = global 128-row block) -> gbuf.
//   mode 1: leaf pass (gate 3, A = Aleaf, tanh epilogue into level-7 Az).
// ---------------------------------------------------------------------------
__global__ __launch_bounds__(256, 2)
void gemm_kernel(int mode, const float* __restrict__ bW)
{
    __shared__ __align__(16) __half sA[2][128][40];
    __shared__ __align__(16) __half sB[2][128][40];

    const int tid  = threadIdx.x;
    const int wid  = tid >> 5;
    const int lane = tid & 31;
    const int grp  = lane >> 2;
    const int tig  = lane & 3;
    const int wm   = wid & 1;
    const int wn   = wid >> 1;
    const int row0 = (int)blockIdx.y * 128;
    const int slot = (mode == 1) ? 3 : (int)blockIdx.x;
    const int nch  = 4;                       // K=128 for Wx/leaf

    const __half* A = (mode == 1) ? g_Aleaf : g_Az;
    const int astride = (mode == 1) ? 128 : 384;
    const size_t gbase = (size_t)slot * 32768;

    float acc[4][4][4];
#pragma unroll
    for (int i = 0; i < 4; i++)
#pragma unroll
        for (int j = 0; j < 4; j++)
#pragma unroll
            for (int q = 0; q < 4; q++) acc[i][j][q] = 0.f;

    const uint32_t sabase = (uint32_t)__cvta_generic_to_shared(&sA[0][0][0]);
    const uint32_t sbbase = (uint32_t)__cvta_generic_to_shared(&sB[0][0][0]);
    const int srow = tid >> 1;
    const int sseg = (tid & 1) * 2;
    const size_t arowoff = (size_t)(row0 + srow) * astride;

    auto issue = [&](int c, int buf) {
        const __half* ap = A + arowoff + c * 32 + sseg * 8;
        const __half* bp = g_Bc + gbase + (size_t)srow * 256 + c * 32 + sseg * 8;
        const uint32_t da = sabase + (uint32_t)((buf * 128 + srow) * 80 + sseg * 16);
        const uint32_t db = sbbase + (uint32_t)((buf * 128 + srow) * 80 + sseg * 16);
        cp16(da,      ap);
        cp16(da + 16, (const char*)ap + 16);
        cp16(db,      bp);
        cp16(db + 16, (const char*)bp + 16);
        asm volatile("cp.async.commit_group;" ::: "memory");
    };

    issue(0, 0);
    for (int ci = 0; ci < nch; ci++) {
        if (ci + 1 < nch) {
            issue(ci + 1, (ci + 1) & 1);
            asm volatile("cp.async.wait_group 1;" ::: "memory");
        } else {
            asm volatile("cp.async.wait_group 0;" ::: "memory");
        }
        __syncthreads();
        const int buf = ci & 1;
#pragma unroll
        for (int ks = 0; ks < 2; ks++) {
            const int k0 = ks * 16;
            uint32_t a[4][4], b[4][2];
#pragma unroll
            for (int i = 0; i < 4; i++) {
                const int r = wm * 64 + i * 16 + grp;
                a[i][0] = *(const uint32_t*)&sA[buf][r    ][k0 + tig * 2];
                a[i][1] = *(const uint32_t*)&sA[buf][r + 8][k0 + tig * 2];
                a[i][2] = *(const uint32_t*)&sA[buf][r    ][k0 + 8 + tig * 2];
                a[i][3] = *(const uint32_t*)&sA[buf][r + 8][k0 + 8 + tig * 2];
            }
#pragma unroll
            for (int j = 0; j < 4; j++) {
                const int n = wn * 32 + j * 8 + grp;
                b[j][0] = *(const uint32_t*)&sB[buf][n][k0 + tig * 2];
                b[j][1] = *(const uint32_t*)&sB[buf][n][k0 + 8 + tig * 2];
            }
#pragma unroll
            for (int i = 0; i < 4; i++)
#pragma unroll
                for (int j = 0; j < 4; j++)
                    asm volatile(
                        "mma.sync.aligned.m16n8k16.row.col.f32.f16.f16.f32 "
                        "{%0,%1,%2,%3}, {%4,%5,%6,%7}, {%8,%9}, {%0,%1,%2,%3};"
                        : "+f"(acc[i][j][0]), "+f"(acc[i][j][1]),
                          "+f"(acc[i][j][2]), "+f"(acc[i][j][3])
                        : "r"(a[i][0]), "r"(a[i][1]), "r"(a[i][2]), "r"(a[i][3]),
                          "r"(b[j][0]), "r"(b[j][1]));
        }
        __syncthreads();
    }

    if (mode == 2) {
        const int gcb = slot * 128 + wn * 32;
#pragma unroll
        for (int i = 0; i < 4; i++) {
            const int lr = wm * 64 + i * 16 + grp;
            const size_t r0 = (size_t)(row0 + lr) * 1664;
            const size_t r1 = (size_t)(row0 + lr + 8) * 1664;
#pragma unroll
            for (int j = 0; j < 4; j++) {
                const int col = gcb + j * 8 + tig * 2;
                *(__half2*)&g_gbuf[r0 + col] = __floats2half2_rn(acc[i][j][0], acc[i][j][1]);
                *(__half2*)&g_gbuf[r1 + col] = __floats2half2_rn(acc[i][j][2], acc[i][j][3]);
            }
        }
    } else {
        // Leaf: h = tanh(acc + bW[3]) -> level-7 Az h-slots (off(7) = 0).
#pragma unroll
        for (int j = 0; j < 4; j++) {
            const int col = wn * 32 + j * 8 + tig * 2;
            const float b0 = __ldg(&bW[384 + col]);
            const float b1 = __ldg(&bW[384 + col + 1]);
#pragma unroll
            for (int i = 0; i < 4; i++) {
#pragma unroll
                for (int half = 0; half < 2; half++) {
                    const int lr = row0 + wm * 64 + i * 16 + grp + half * 8;
                    const float h0 = tanh_(acc[i][j][half * 2 + 0] + b0);
                    const float h1 = tanh_(acc[i][j][half * 2 + 1] + b1);
                    const int bb = lr >> 8, nn = lr & 255;
                    const int prow = (bb << 7) + (nn >> 1);
                    const int side = nn & 1;
                    const size_t o = (size_t)prow * 384 + 128 + side * 128 + col;
                    *(__half2*)&g_Az[o] = __floats2half2_rn(h0, h1);
                }
            }
        }
    }
}

// ---------------------------------------------------------------------------
// Fused per-level kernel: recurrent gates GEMM + in-kernel pointwise.
// blockIdx.x = list (0 = binary -> slots 4..8 K=256; 1 = unary -> slots 9..12
// K=128), blockIdx.y = 128-row tile of the compacted list. After computing all
// gates for its rows (spilled to gbuf, L2-hot), the block performs the LSTM
// cell update for those rows: arity is implied by list membership.
// ---------------------------------------------------------------------------
__global__ __launch_bounds__(256, 2)
void level_fused_kernel(int l, int off, int poff, int cin, int czero,
                        const float* __restrict__ bW,
                        const float* __restrict__ bUbin,
                        const float* __restrict__ bUun,
                        float* __restrict__ out)
{
    __shared__ __align__(16) __half sA[2][128][40];
    __shared__ __align__(16) __half sB[2][128][40];
    __shared__ int sIdx[128];

    const int which = (int)blockIdx.x;          // 0 = binary, 1 = unary
    const int row0  = (int)blockIdx.y * 128;
    const int count = g_cnt[l][which];
    if (row0 >= count) return;

    const int tid  = threadIdx.x;
    const int wid  = tid >> 5;
    const int lane = tid & 31;
    const int grp  = lane >> 2;
    const int tig  = lane & 3;
    const int wm   = wid & 1;
    const int wn   = wid >> 1;

    if (tid < 128) {
        int s = row0 + tid;
        if (s >= count) s = count - 1;          // clamp (duplicates benign)
        sIdx[tid] = g_list[l][which][s];
    }
    __syncthreads();

    const int ngates = which ? 4 : 5;
    const int slot0  = which ? 9 : 4;
    const int nch    = which ? 4 : 8;           // K=128 : K=256

    const uint32_t sabase = (uint32_t)__cvta_generic_to_shared(&sA[0][0][0]);
    const uint32_t sbbase = (uint32_t)__cvta_generic_to_shared(&sB[0][0][0]);
    const int srow = tid >> 1;
    const int sseg = (tid & 1) * 2;
    const size_t arowoff = (size_t)(off + sIdx[srow]) * 384 + 128;  // h slots

    for (int gg = 0; gg < ngates; gg++) {
        const int slot = slot0 + gg;
        const size_t gbase = (size_t)slot * 32768;

        float acc[4][4][4];
#pragma unroll
        for (int i = 0; i < 4; i++)
#pragma unroll
            for (int j = 0; j < 4; j++)
#pragma unroll
                for (int q = 0; q < 4; q++) acc[i][j][q] = 0.f;

        auto issue = [&](int c, int buf) {
            const __half* ap = g_Az + arowoff + c * 32 + sseg * 8;
            const __half* bp = g_Bc + gbase + (size_t)srow * 256 + c * 32 + sseg * 8;
            const uint32_t da = sabase + (uint32_t)((buf * 128 + srow) * 80 + sseg * 16);
            const uint32_t db = sbbase + (uint32_t)((buf * 128 + srow) * 80 + sseg * 16);
            cp16(da,      ap);
            cp16(da + 16, (const char*)ap + 16);
            cp16(db,      bp);
            cp16(db + 16, (const char*)bp + 16);
            asm volatile("cp.async.commit_group;" ::: "memory");
        };

        issue(0, 0);
        for (int ci = 0; ci < nch; ci++) {
            if (ci + 1 < nch) {
                issue(ci + 1, (ci + 1) & 1);
                asm volatile("cp.async.wait_group 1;" ::: "memory");
            } else {
                asm volatile("cp.async.wait_group 0;" ::: "memory");
            }
            __syncthreads();
            const int buf = ci & 1;
#pragma unroll
            for (int ks = 0; ks < 2; ks++) {
                const int k0 = ks * 16;
                uint32_t a[4][4], b[4][2];
#pragma unroll
                for (int i = 0; i < 4; i++) {
                    const int r = wm * 64 + i * 16 + grp;
                    a[i][0] = *(const uint32_t*)&sA[buf][r    ][k0 + tig * 2];
                    a[i][1] = *(const uint32_t*)&sA[buf][r + 8][k0 + tig * 2];
                    a[i][2] = *(const uint32_t*)&sA[buf][r    ][k0 + 8 + tig * 2];
                    a[i][3] = *(const uint32_t*)&sA[buf][r + 8][k0 + 8 + tig * 2];
                }
#pragma unroll
                for (int j = 0; j < 4; j++) {
                    const int n = wn * 32 + j * 8 + grp;
                    b[j][0] = *(const uint32_t*)&sB[buf][n][k0 + tig * 2];
                    b[j][1] = *(const uint32_t*)&sB[buf][n][k0 + 8 + tig * 2];
                }
#pragma unroll
                for (int i = 0; i < 4; i++)
#pragma unroll
                    for (int j = 0; j < 4; j++)
                        asm volatile(
                            "mma.sync.aligned.m16n8k16.row.col.f32.f16.f16.f32 "
                            "{%0,%1,%2,%3}, {%4,%5,%6,%7}, {%8,%9}, {%0,%1,%2,%3};"
                            : "+f"(acc[i][j][0]), "+f"(acc[i][j][1]),
                              "+f"(acc[i][j][2]), "+f"(acc[i][j][3])
                            : "r"(a[i][0]), "r"(a[i][1]), "r"(a[i][2]), "r"(a[i][3]),
                              "r"(b[j][0]), "r"(b[j][1]));
            }
            __syncthreads();
        }

        // Spill this gate's tile to gbuf (L2-hot; consumed below)
        const int gcb = slot * 128 + wn * 32;
#pragma unroll
        for (int i = 0; i < 4; i++) {
            const int lr = wm * 64 + i * 16 + grp;
            const size_t r0 = (size_t)(off + sIdx[lr])     * 1664;
            const size_t r1 = (size_t)(off + sIdx[lr + 8]) * 1664;
#pragma unroll
            for (int j = 0; j < 4; j++) {
                const int col = gcb + j * 8 + tig * 2;
                *(__half2*)&g_gbuf[r0 + col] = __floats2half2_rn(acc[i][j][0], acc[i][j][1]);
                *(__half2*)&g_gbuf[r1 + col] = __floats2half2_rn(acc[i][j][2], acc[i][j][3]);
            }
        }
    }

    // Block-wide visibility of this block's gbuf writes
    __syncthreads();

    // ---- In-kernel pointwise for this tile's rows ----
    const int col = tid & 127;
    const int sub = tid >> 7;
    const float bw0 = __ldg(&bW[0 * 128 + col]);
    const float bw1 = __ldg(&bW[1 * 128 + col]);
    const float bw2 = __ldg(&bW[2 * 128 + col]);
    const float bw3 = __ldg(&bW[3 * 128 + col]);

    for (int r = sub; r < 128; r += 2) {
        if (row0 + r >= count) break;            // skip clamped duplicates
        const int row = sIdx[r];
        const int b = row >> l;
        const int n = row - (b << l);
        const size_t childrow = ((size_t)b << (l + 1)) + 2 * n;
        const __half* gb = g_gbuf + (size_t)(off + row) * 1664;

        const float wx0 = __half2float(gb[0 * 128 + col]) + bw0;
        const float wx1 = __half2float(gb[1 * 128 + col]) + bw1;
        const float wx2 = __half2float(gb[2 * 128 + col]) + bw2;
        const float wx3 = __half2float(gb[3 * 128 + col]) + bw3;
        const float cl = czero ? 0.f : g_cbuf[cin][childrow * 128 + col];

        float hv, cv;
        if (which == 0) {   // binary
            const float cr = czero ? 0.f : g_cbuf[cin][(childrow + 1) * 128 + col];
            const float ig = sigmoid_(wx0 + __half2float(gb[4 * 128 + col]) + __ldg(&bUbin[0 * 128 + col]));
            const float fl = sigmoid_(wx1 + __half2float(gb[5 * 128 + col]) + __ldg(&bUbin[1 * 128 + col]));
            const float fr = sigmoid_(wx1 + __half2float(gb[6 * 128 + col]) + __ldg(&bUbin[2 * 128 + col]));
            const float og = sigmoid_(wx2 + __half2float(gb[7 * 128 + col]) + __ldg(&bUbin[3 * 128 + col]));
            const float ug = tanh_   (wx3 + __half2float(gb[8 * 128 + col]) + __ldg(&bUbin[4 * 128 + col]));
            cv = ig * ug + fl * cl + fr * cr;
            hv = og * tanh_(cv);
        } else {            // unary
            const float ig = sigmoid_(wx0 + __half2float(gb[ 9 * 128 + col]) + __ldg(&bUun[0 * 128 + col]));
            const float fg = sigmoid_(wx1 + __half2float(gb[10 * 128 + col]) + __ldg(&bUun[1 * 128 + col]));
            const float og = sigmoid_(wx2 + __half2float(gb[11 * 128 + col]) + __ldg(&bUun[2 * 128 + col]));
            const float ug = tanh_   (wx3 + __half2float(gb[12 * 128 + col]) + __ldg(&bUun[3 * 128 + col]));
            cv = ig * ug + fg * cl;
            hv = og * tanh_(cv);
        }

        g_cbuf[1 - cin][(size_t)row * 128 + col] = cv;

        if (l == 0) {
            out[row * 128 + col] = hv;
            out[BATCH * HDIM + row * 128 + col] = cv;
        } else {
            const int prow = (b << (l - 1)) + (n >> 1);
            const int side = n & 1;
            g_Az[(size_t)(poff + prow) * 384 + 128 + side * 128 + col] =
                __float2half_rn(hv);
        }
    }
}

// ---------------------------------------------------------------------------
extern "C" void kernel_launch(void* const* d_in, const int* in_sizes, int n_in,
                              void* d_out, int out_size)
{
    const int*   tokens = (const int*)  d_in[0];
    const int*   arity  = (const int*)  d_in[1];
    const float* emb    = (const float*)d_in[2];
    const float* W      = (const float*)d_in[3];
    const float* bW     = (const float*)d_in[4];
    const float* Ubin   = (const float*)d_in[5];
    const float* bUbin  = (const float*)d_in[6];
    const float* Uun    = (const float*)d_in[7];
    const float* bUun   = (const float*)d_in[8];
    float* out = (float*)d_out;

    prep_B_kernel<<<(13 * 128 * 256 + 255) / 256, 256>>>(W, Ubin, Uun);
    stage_leaf_kernel<<<(65536 * 128) / 256, 256>>>(tokens, emb);
    stage_x_all_kernel<<<(AZROWS * 128) / 256, 256>>>(tokens, emb);
    classify_all_kernel<<<AZROWS / 256, 256>>>(arity);

    // Leaf GEMM (gate 3 = W[3]) -> level-7 Az h-slots
    {
        dim3 grid(1, 65536 / 128);
        gemm_kernel<<<grid, 256>>>(1, bW);
    }

    // Wx gates (slots 0..3) for ALL levels in one dense GEMM (x-only inputs)
    {
        dim3 grid(4, AZROWS / 128);
        gemm_kernel<<<grid, 256>>>(2, bW);
    }

    // Levels 7..0: ONE fused kernel per level (recurrent gates + pointwise)
    for (int l = 7; l >= 0; l--) {
        const int rows = BATCH << l;
        const int off  = 256 * (256 - (2 << l));
        const int poff = (l > 0) ? 256 * (256 - (1 << l)) : 0;
        const int cin  = (7 - l) & 1;
        dim3 ggrid(2, rows / 128);
        level_fused_kernel<<<ggrid, 256>>>(l, off, poff, cin, (l == 7) ? 1 : 0,
                                           bW, bUbin, bUun,
                                           (l == 0) ? out : nullptr);
    }
}

// round 16
// speedup vs baseline: 4.4302x; 4.4302x over previous
#include <cuda_runtime.h>
#include <cuda_fp16.h>
#include <cstdint>
#include <math.h>

#define BATCH 256
#define HDIM  128
#define NTOK  511
#define NARITY 255
#define AZROWS 65280   // sum over levels 0..7 of 256*2^l

// ---------------------------------------------------------------------------
// Static device scratch (allocation-free rule):
//   Bc   : combined transposed weights [13 gates][n=128][k=256] fp16
//   Aleaf: leaf embeddings [65536][128] fp16
//   Az   : ALL levels' inputs [65280 rows][384 k] fp16, level l at row
//          off(l) = 256*(256 - 2^(l+1))  (x 0..127 | h_l 128..255 | h_r 256..383)
//   gbuf : gate pre-activations [32768][13*128] fp16 (reused per level)
//   cbuf : cell-state ping-pong [2][65536][128] fp32
//   list/cnt : per-level arity-compacted LOCAL row lists (0=binary, 1=unary)
// ---------------------------------------------------------------------------
__device__ __align__(16) __half g_Bc[13 * 128 * 256];
__device__ __align__(16) __half g_Aleaf[65536 * 128];
__device__ __align__(16) __half g_Az[AZROWS * 384];
__device__ __align__(16) __half g_gbuf[32768 * 1664];
__device__ __align__(16) float  g_cbuf[2][65536 * 128];
__device__ int g_list[8][2][32768];
__device__ int g_cnt[8][2];

__device__ __forceinline__ float sigmoid_(float x) { return 1.0f / (1.0f + expf(-x)); }
__device__ __forceinline__ float tanh_(float x)    { return 1.0f - 2.0f / (expf(2.0f * x) + 1.0f); }

__device__ __forceinline__ void cp16(uint32_t dst, const void* src) {
    asm volatile("cp.async.ca.shared.global [%0], [%1], 16;" :: "r"(dst), "l"(src));
}

// ---------------------------------------------------------------------------
// prep_B: weights -> fp16 combined-B; zeroes the per-level counters.
// ---------------------------------------------------------------------------
__global__ void prep_B_kernel(const float* __restrict__ W,
                              const float* __restrict__ Ubin,
                              const float* __restrict__ Uun)
{
    const int idx = blockIdx.x * 256 + threadIdx.x;
    if (idx < 16) ((int*)g_cnt)[idx] = 0;
    if (idx >= 13 * 128 * 256) return;
    const int g = idx >> 15;
    const int n = (idx >> 8) & 127;
    const int k = idx & 255;
    float v;
    if (g < 4)       v = (k < 128) ? W[g * 16384 + k * 128 + n] : 0.f;
    else if (g < 9)  v = Ubin[(g - 4) * 32768 + k * 128 + n];
    else             v = (k < 128) ? Uun[(g - 9) * 16384 + k * 128 + n] : 0.f;
    g_Bc[idx] = __float2half_rn(v);
}

// Decode global Az row -> (level, level base offset).
__device__ __forceinline__ void az_decode(int grow, int& l, int& off)
{
    const int u = AZROWS - grow;
    const int w = (u - 1) >> 8;
    l = 31 - __clz(w + 1);
    off = 256 * (256 - (2 << l));
}

// ---------------------------------------------------------------------------
// stage_all: leaf embeddings AND all levels' x inputs in ONE launch.
//   idx < 65536*128          : Aleaf[row][col] = emb[tok_leaf]
//   idx >= 65536*128         : Az[grow][col]   = emb[tok_level]
// ---------------------------------------------------------------------------
#define LEAF_ELEMS (65536 * 128)
__global__ void stage_all_kernel(const int* __restrict__ tokens,
                                 const float* __restrict__ emb)
{
    const int idx = blockIdx.x * 256 + threadIdx.x;
    if (idx < LEAF_ELEMS) {
        const int row = idx >> 7;
        const int col = idx & 127;
        const int b = row >> 8, n = row & 255;
        const int tok = __ldg(&tokens[b * NTOK + 255 + n]);
        g_Aleaf[idx] = __float2half_rn(__ldg(&emb[(size_t)tok * 128 + col]));
    } else {
        const int i2 = idx - LEAF_ELEMS;       // 0 .. AZROWS*128-1
        const int grow = i2 >> 7;
        const int col  = i2 & 127;
        int l, off;
        az_decode(grow, l, off);
        const int local = grow - off;
        const int b = local >> l;
        const int n = local - (b << l);
        const int tok = __ldg(&tokens[b * NTOK + ((1 << l) - 1) + n]);
        g_Az[(size_t)grow * 384 + col] =
            __float2half_rn(__ldg(&emb[(size_t)tok * 128 + col]));
    }
}

// Classify all levels' nodes; warp-aggregated atomics (warps are level-uniform
// because level boundaries are multiples of 256 rows).
__global__ void classify_all_kernel(const int* __restrict__ arity)
{
    const int grow = blockIdx.x * 256 + threadIdx.x;  // exact cover of AZROWS
    const int lane = threadIdx.x & 31;
    int l, off;
    az_decode(grow, l, off);
    const int local = grow - off;
    const int b = local >> l;
    const int n = local - (b << l);
    const int ar = __ldg(&arity[b * NARITY + ((1 << l) - 1) + n]);
    const int w = (ar == 1) ? 0 : 1;
    const unsigned m0 = __ballot_sync(0xffffffffu, w == 0);
    const unsigned mym = w ? ~m0 : m0;
    const int rank   = __popc(mym & ((1u << lane) - 1u));
    const int leader = __ffs(mym) - 1;
    int base = 0;
    if (lane == leader) base = atomicAdd(&g_cnt[l][w], __popc(mym));
    base = __shfl_sync(0xffffffffu, base, leader);
    g_list[l][w][base + rank] = local;
}

// ---------------------------------------------------------------------------
// Fused per-level GEMM. blockIdx.x = gate slot:
//   0..3  : Wx gates, dense over all level rows (K=128, x slots)
//   4..8  : Ubin gates over binary-compacted rows (K=256, h slots)
//   9..12 : Uun  gates over unary-compacted rows (K=128, h_l slot)
// mode 1 = leaf pass (gate 3 only, A = Aleaf, tanh epilogue into level-7 Az).
// mma.sync m16n8k16 fp16, 128x128 block tile, 8 warps 2(M)x4(N), KC=32,
// cp.async double-buffered.
// ---------------------------------------------------------------------------
__global__ __launch_bounds__(256, 2)
void gemm_kernel(int mode, int l, int off, const float* __restrict__ bW)
{
    __shared__ __align__(16) __half sA[2][128][40];
    __shared__ __align__(16) __half sB[2][128][40];
    __shared__ int sIdx[128];

    const int tid  = threadIdx.x;
    const int wid  = tid >> 5;
    const int lane = tid & 31;
    const int grp  = lane >> 2;
    const int tig  = lane & 3;
    const int wm   = wid & 1;
    const int wn   = wid >> 1;
    const int slot = (mode == 1) ? 3 : (int)blockIdx.x;
    const int row0 = (int)blockIdx.y * 128;

    int nch, akb, which;
    if (mode == 1 || slot < 4) { nch = 4; akb = 0;   which = -1; }
    else if (slot < 9)         { nch = 8; akb = 128; which = 0;  }
    else                       { nch = 4; akb = 128; which = 1;  }

    const int srow = tid >> 1;
    const int sseg = (tid & 1) * 2;

    size_t arowoff;
    if (mode == 1) {
        arowoff = (size_t)(row0 + srow) * 128;
    } else if (which < 0) {
        arowoff = (size_t)(off + row0 + srow) * 384;
    } else {
        const int count = g_cnt[l][which];
        if (row0 >= count) return;                  // uniform skip
        if (tid < 128) {
            int s = row0 + tid;
            if (s >= count) s = count - 1;          // clamp: duplicate writes, benign
            sIdx[tid] = g_list[l][which][s];
        }
        __syncthreads();
        arowoff = (size_t)(off + sIdx[srow]) * 384;
    }

    const __half* A = (mode == 1) ? g_Aleaf : g_Az;
    const size_t gbase = (size_t)slot * 32768;

    float acc[4][4][4];
#pragma unroll
    for (int i = 0; i < 4; i++)
#pragma unroll
        for (int j = 0; j < 4; j++)
#pragma unroll
            for (int q = 0; q < 4; q++) acc[i][j][q] = 0.f;

    const uint32_t sabase = (uint32_t)__cvta_generic_to_shared(&sA[0][0][0]);
    const uint32_t sbbase = (uint32_t)__cvta_generic_to_shared(&sB[0][0][0]);

    auto issue = [&](int c, int buf) {
        const __half* ap = A + arowoff + akb + c * 32 + sseg * 8;
        const __half* bp = g_Bc + gbase + (size_t)srow * 256 + c * 32 + sseg * 8;
        const uint32_t da = sabase + (uint32_t)((buf * 128 + srow) * 80 + sseg * 16);
        const uint32_t db = sbbase + (uint32_t)((buf * 128 + srow) * 80 + sseg * 16);
        cp16(da,      ap);
        cp16(da + 16, (const char*)ap + 16);
        cp16(db,      bp);
        cp16(db + 16, (const char*)bp + 16);
        asm volatile("cp.async.commit_group;" ::: "memory");
    };

    issue(0, 0);
    for (int ci = 0; ci < nch; ci++) {
        if (ci + 1 < nch) {
            issue(ci + 1, (ci + 1) & 1);
            asm volatile("cp.async.wait_group 1;" ::: "memory");
        } else {
            asm volatile("cp.async.wait_group 0;" ::: "memory");
        }
        __syncthreads();
        const int buf = ci & 1;
#pragma unroll
        for (int ks = 0; ks < 2; ks++) {
            const int k0 = ks * 16;
            uint32_t a[4][4], b[4][2];
#pragma unroll
            for (int i = 0; i < 4; i++) {
                const int r = wm * 64 + i * 16 + grp;
                a[i][0] = *(const uint32_t*)&sA[buf][r    ][k0 + tig * 2];
                a[i][1] = *(const uint32_t*)&sA[buf][r + 8][k0 + tig * 2];
                a[i][2] = *(const uint32_t*)&sA[buf][r    ][k0 + 8 + tig * 2];
                a[i][3] = *(const uint32_t*)&sA[buf][r + 8][k0 + 8 + tig * 2];
            }
#pragma unroll
            for (int j = 0; j < 4; j++) {
                const int n = wn * 32 + j * 8 + grp;
                b[j][0] = *(const uint32_t*)&sB[buf][n][k0 + tig * 2];
                b[j][1] = *(const uint32_t*)&sB[buf][n][k0 + 8 + tig * 2];
            }
#pragma unroll
            for (int i = 0; i < 4; i++)
#pragma unroll
                for (int j = 0; j < 4; j++)
                    asm volatile(
                        "mma.sync.aligned.m16n8k16.row.col.f32.f16.f16.f32 "
                        "{%0,%1,%2,%3}, {%4,%5,%6,%7}, {%8,%9}, {%0,%1,%2,%3};"
                        : "+f"(acc[i][j][0]), "+f"(acc[i][j][1]),
                          "+f"(acc[i][j][2]), "+f"(acc[i][j][3])
                        : "r"(a[i][0]), "r"(a[i][1]), "r"(a[i][2]), "r"(a[i][3]),
                          "r"(b[j][0]), "r"(b[j][1]));
        }
        __syncthreads();
    }

    // ---- Epilogue ----
    if (mode == 0) {
        const int gcb = slot * 128 + wn * 32;
#pragma unroll
        for (int i = 0; i < 4; i++) {
            const int lr = wm * 64 + i * 16 + grp;
            size_t r0, r1;
            if (which < 0) { r0 = (size_t)(row0 + lr) * 1664; r1 = (size_t)(row0 + lr + 8) * 1664; }
            else           { r0 = (size_t)sIdx[lr] * 1664;    r1 = (size_t)sIdx[lr + 8] * 1664;    }
#pragma unroll
            for (int j = 0; j < 4; j++) {
                const int col = gcb + j * 8 + tig * 2;
                *(__half2*)&g_gbuf[r0 + col] = __floats2half2_rn(acc[i][j][0], acc[i][j][1]);
                *(__half2*)&g_gbuf[r1 + col] = __floats2half2_rn(acc[i][j][2], acc[i][j][3]);
            }
        }
    } else {
        // Leaf: h = tanh(acc + bW[3]) -> level-7 Az h-slots (off(7) = 0).
#pragma unroll
        for (int j = 0; j < 4; j++) {
            const int col = wn * 32 + j * 8 + tig * 2;
            const float b0 = __ldg(&bW[384 + col]);
            const float b1 = __ldg(&bW[384 + col + 1]);
#pragma unroll
            for (int i = 0; i < 4; i++) {
#pragma unroll
                for (int half = 0; half < 2; half++) {
                    const int lr = row0 + wm * 64 + i * 16 + grp + half * 8;
                    const float h0 = tanh_(acc[i][j][half * 2 + 0] + b0);
                    const float h1 = tanh_(acc[i][j][half * 2 + 1] + b1);
                    const int bb = lr >> 8, nn = lr & 255;
                    const int prow = (bb << 7) + (nn >> 1);
                    const int side = nn & 1;
                    const size_t o = (size_t)prow * 384 + 128 + side * 128 + col;
                    *(__half2*)&g_Az[o] = __floats2half2_rn(h0, h1);
                }
            }
        }
    }
}

// ---------------------------------------------------------------------------
// Pointwise LSTM cell update for level l. czero: children are leaves (c = 0).
// ---------------------------------------------------------------------------
__global__ __launch_bounds__(128)
void pointwise_kernel(int l, int cin, int czero, int poff,
                      const int* __restrict__ arity,
                      const float* __restrict__ bW,
                      const float* __restrict__ bUbin,
                      const float* __restrict__ bUun,
                      float* __restrict__ out)
{
    const int row = blockIdx.x;
    const int col = threadIdx.x;
    const int b = row >> l;
    const int n = row - (b << l);
    const int ar = __ldg(&arity[b * NARITY + ((1 << l) - 1) + n]);
    const size_t childrow = ((size_t)b << (l + 1)) + 2 * n;
    const float cl = czero ? 0.f : g_cbuf[cin][childrow * 128 + col];
    const float cr = czero ? 0.f : g_cbuf[cin][(childrow + 1) * 128 + col];
    const __half* gb = g_gbuf + (size_t)row * 1664;

    const float wx0 = __half2float(gb[0 * 128 + col]) + __ldg(&bW[0 * 128 + col]);
    const float wx1 = __half2float(gb[1 * 128 + col]) + __ldg(&bW[1 * 128 + col]);
    const float wx2 = __half2float(gb[2 * 128 + col]) + __ldg(&bW[2 * 128 + col]);
    const float wx3 = __half2float(gb[3 * 128 + col]) + __ldg(&bW[3 * 128 + col]);

    float hv, cv;
    if (ar == 1) {
        const float ig = sigmoid_(wx0 + __half2float(gb[4 * 128 + col]) + __ldg(&bUbin[0 * 128 + col]));
        const float fl = sigmoid_(wx1 + __half2float(gb[5 * 128 + col]) + __ldg(&bUbin[1 * 128 + col]));
        const float fr = sigmoid_(wx1 + __half2float(gb[6 * 128 + col]) + __ldg(&bUbin[2 * 128 + col]));
        const float og = sigmoid_(wx2 + __half2float(gb[7 * 128 + col]) + __ldg(&bUbin[3 * 128 + col]));
        const float ug = tanh_   (wx3 + __half2float(gb[8 * 128 + col]) + __ldg(&bUbin[4 * 128 + col]));
        cv = ig * ug + fl * cl + fr * cr;
        hv = og * tanh_(cv);
    } else {
        const float ig = sigmoid_(wx0 + __half2float(gb[ 9 * 128 + col]) + __ldg(&bUun[0 * 128 + col]));
        const float fg = sigmoid_(wx1 + __half2float(gb[10 * 128 + col]) + __ldg(&bUun[1 * 128 + col]));
        const float og = sigmoid_(wx2 + __half2float(gb[11 * 128 + col]) + __ldg(&bUun[2 * 128 + col]));
        const float ug = tanh_   (wx3 + __half2float(gb[12 * 128 + col]) + __ldg(&bUun[3 * 128 + col]));
        cv = ig * ug + fg * cl;
        hv = og * tanh_(cv);
    }

    g_cbuf[1 - cin][(size_t)row * 128 + col] = cv;

    if (l == 0) {
        out[row * 128 + col] = hv;
        out[BATCH * HDIM + row * 128 + col] = cv;
    } else {
        const int prow = (b << (l - 1)) + (n >> 1);
        const int side = n & 1;
        g_Az[(size_t)(poff + prow) * 384 + 128 + side * 128 + col] =
            __float2half_rn(hv);
    }
}

// ---------------------------------------------------------------------------
extern "C" void kernel_launch(void* const* d_in, const int* in_sizes, int n_in,
                              void* d_out, int out_size)
{
    const int*   tokens = (const int*)  d_in[0];
    const int*   arity  = (const int*)  d_in[1];
    const float* emb    = (const float*)d_in[2];
    const float* W      = (const float*)d_in[3];
    const float* bW     = (const float*)d_in[4];
    const float* Ubin   = (const float*)d_in[5];
    const float* bUbin  = (const float*)d_in[6];
    const float* Uun    = (const float*)d_in[7];
    const float* bUun   = (const float*)d_in[8];
    float* out = (float*)d_out;

    prep_B_kernel<<<(13 * 128 * 256 + 255) / 256, 256>>>(W, Ubin, Uun);
    stage_all_kernel<<<(LEAF_ELEMS + AZROWS * 128) / 256, 256>>>(tokens, emb);
    classify_all_kernel<<<AZROWS / 256, 256>>>(arity);

    // Leaf GEMM (gate 3 = W[3]) -> level-7 Az h-slots
    {
        dim3 grid(1, 65536 / 128);
        gemm_kernel<<<grid, 256>>>(1, 7, 0, bW);
    }

    // Levels 7..0: one fused GEMM + one pointwise per level
    for (int l = 7; l >= 0; l--) {
        const int rows = BATCH << l;
        const int off  = 256 * (256 - (2 << l));
        const int poff = (l > 0) ? 256 * (256 - (1 << l)) : 0;
        const int cin  = (7 - l) & 1;
        dim3 ggrid(13, rows / 128);
        gemm_kernel<<<ggrid, 256>>>(0, l, off, bW);
        pointwise_kernel<<<rows, 128>>>(l, cin, (l == 7) ? 1 : 0, poff,
                                        arity, bW, bUbin, bUun,
                                        (l == 0) ? out : nullptr);
    }
}

// round 17
// speedup vs baseline: 4.6334x; 1.0459x over previous
#include <cuda_runtime.h>
#include <cuda_fp16.h>
#include <cstdint>
#include <math.h>

#define BATCH 256
#define HDIM  128
#define NTOK  511
#define NARITY 255
#define AZROWS 65280   // sum over levels 0..7 of 256*2^l

// ---------------------------------------------------------------------------
// Static device scratch (allocation-free rule):
//   Bc   : combined transposed weights [13 gates][n=128][k=256] fp16
//   Aleaf: leaf embeddings [65536][128] fp16
//   Az   : ALL levels' inputs [65280 rows][384 k] fp16, level l at row
//          off(l) = 256*(256 - 2^(l+1))  (x 0..127 | h_l 128..255 | h_r 256..383)
//   gbuf : gate pre-activations [32768][13*128] fp16 (reused per level)
//   cbuf : cell-state ping-pong [2][65536][128] fp32
//   list/cnt : per-level arity-compacted LOCAL row lists (0=binary, 1=unary)
// ---------------------------------------------------------------------------
__device__ __align__(16) __half g_Bc[13 * 128 * 256];
__device__ __align__(16) __half g_Aleaf[65536 * 128];
__device__ __align__(16) __half g_Az[AZROWS * 384];
__device__ __align__(16) __half g_gbuf[32768 * 1664];
__device__ __align__(16) float  g_cbuf[2][65536 * 128];
__device__ int g_list[8][2][32768];
__device__ int g_cnt[8][2];

__device__ __forceinline__ float sigmoid_(float x) { return 1.0f / (1.0f + expf(-x)); }
__device__ __forceinline__ float tanh_(float x)    { return 1.0f - 2.0f / (expf(2.0f * x) + 1.0f); }

__device__ __forceinline__ void cp16(uint32_t dst, const void* src) {
    asm volatile("cp.async.ca.shared.global [%0], [%1], 16;" :: "r"(dst), "l"(src));
}

// ---------------------------------------------------------------------------
// prep_B: weights -> fp16 combined-B; zeroes the per-level counters.
// ---------------------------------------------------------------------------
__global__ void prep_B_kernel(const float* __restrict__ W,
                              const float* __restrict__ Ubin,
                              const float* __restrict__ Uun)
{
    const int idx = blockIdx.x * 256 + threadIdx.x;
    if (idx < 16) ((int*)g_cnt)[idx] = 0;
    if (idx >= 13 * 128 * 256) return;
    const int g = idx >> 15;
    const int n = (idx >> 8) & 127;
    const int k = idx & 255;
    float v;
    if (g < 4)       v = (k < 128) ? W[g * 16384 + k * 128 + n] : 0.f;
    else if (g < 9)  v = Ubin[(g - 4) * 32768 + k * 128 + n];
    else             v = (k < 128) ? Uun[(g - 9) * 16384 + k * 128 + n] : 0.f;
    g_Bc[idx] = __float2half_rn(v);
}

// Decode global Az row -> (level, level base offset).
__device__ __forceinline__ void az_decode(int grow, int& l, int& off)
{
    const int u = AZROWS - grow;
    const int w = (u - 1) >> 8;
    l = 31 - __clz(w + 1);
    off = 256 * (256 - (2 << l));
}

// ---------------------------------------------------------------------------
// stage_all: leaf embeddings AND all levels' x inputs in ONE launch.
// ---------------------------------------------------------------------------
#define LEAF_ELEMS (65536 * 128)
__global__ void stage_all_kernel(const int* __restrict__ tokens,
                                 const float* __restrict__ emb)
{
    const int idx = blockIdx.x * 256 + threadIdx.x;
    if (idx < LEAF_ELEMS) {
        const int row = idx >> 7;
        const int col = idx & 127;
        const int b = row >> 8, n = row & 255;
        const int tok = __ldg(&tokens[b * NTOK + 255 + n]);
        g_Aleaf[idx] = __float2half_rn(__ldg(&emb[(size_t)tok * 128 + col]));
    } else {
        const int i2 = idx - LEAF_ELEMS;
        const int grow = i2 >> 7;
        const int col  = i2 & 127;
        int l, off;
        az_decode(grow, l, off);
        const int local = grow - off;
        const int b = local >> l;
        const int n = local - (b << l);
        const int tok = __ldg(&tokens[b * NTOK + ((1 << l) - 1) + n]);
        g_Az[(size_t)grow * 384 + col] =
            __float2half_rn(__ldg(&emb[(size_t)tok * 128 + col]));
    }
}

// Classify all levels' nodes; warp-aggregated atomics.
__global__ void classify_all_kernel(const int* __restrict__ arity)
{
    const int grow = blockIdx.x * 256 + threadIdx.x;
    const int lane = threadIdx.x & 31;
    int l, off;
    az_decode(grow, l, off);
    const int local = grow - off;
    const int b = local >> l;
    const int n = local - (b << l);
    const int ar = __ldg(&arity[b * NARITY + ((1 << l) - 1) + n]);
    const int w = (ar == 1) ? 0 : 1;
    const unsigned m0 = __ballot_sync(0xffffffffu, w == 0);
    const unsigned mym = w ? ~m0 : m0;
    const int rank   = __popc(mym & ((1u << lane) - 1u));
    const int leader = __ffs(mym) - 1;
    int base = 0;
    if (lane == leader) base = atomicAdd(&g_cnt[l][w], __popc(mym));
    base = __shfl_sync(0xffffffffu, base, leader);
    g_list[l][w][base + rank] = local;
}

// ---------------------------------------------------------------------------
// Fused per-level GEMM. blockIdx.x = gate slot:
//   0..3  : Wx dense (K=128, x slots)   4..8 : Ubin (K=256, bin list)
//   9..12 : Uun (K=128, un list)        mode 1: leaf (gate 3, A=Aleaf)
// mma.sync m16n8k16 fp16, 128x128 tile, 8 warps 2(M)x4(N), KC=32.
// cp.async double-buffered, ONE barrier per chunk, ldmatrix fragment loads.
// ---------------------------------------------------------------------------
__global__ __launch_bounds__(256, 2)
void gemm_kernel(int mode, int l, int off, const float* __restrict__ bW)
{
    __shared__ __align__(16) __half sA[2][128][40];
    __shared__ __align__(16) __half sB[2][128][40];
    __shared__ int sIdx[128];

    const int tid  = threadIdx.x;
    const int wid  = tid >> 5;
    const int lane = tid & 31;
    const int grp  = lane >> 2;
    const int tig  = lane & 3;
    const int wm   = wid & 1;
    const int wn   = wid >> 1;
    const int slot = (mode == 1) ? 3 : (int)blockIdx.x;
    const int row0 = (int)blockIdx.y * 128;

    int nch, akb, which;
    if (mode == 1 || slot < 4) { nch = 4; akb = 0;   which = -1; }
    else if (slot < 9)         { nch = 8; akb = 128; which = 0;  }
    else                       { nch = 4; akb = 128; which = 1;  }

    const int srow = tid >> 1;
    const int sseg = (tid & 1) * 2;

    size_t arowoff;
    if (mode == 1) {
        arowoff = (size_t)(row0 + srow) * 128;
    } else if (which < 0) {
        arowoff = (size_t)(off + row0 + srow) * 384;
    } else {
        const int count = g_cnt[l][which];
        if (row0 >= count) return;                  // uniform skip
        if (tid < 128) {
            int s = row0 + tid;
            if (s >= count) s = count - 1;          // clamp: duplicate writes, benign
            sIdx[tid] = g_list[l][which][s];
        }
        __syncthreads();
        arowoff = (size_t)(off + sIdx[srow]) * 384;
    }

    const __half* A = (mode == 1) ? g_Aleaf : g_Az;
    const size_t gbase = (size_t)slot * 32768;

    float acc[4][4][4];
#pragma unroll
    for (int i = 0; i < 4; i++)
#pragma unroll
        for (int j = 0; j < 4; j++)
#pragma unroll
            for (int q = 0; q < 4; q++) acc[i][j][q] = 0.f;

    const uint32_t sabase = (uint32_t)__cvta_generic_to_shared(&sA[0][0][0]);
    const uint32_t sbbase = (uint32_t)__cvta_generic_to_shared(&sB[0][0][0]);

    // ldmatrix lane-derived offsets
    const int arow_l = lane & 15;                    // row within 16-row tile
    const int acol_l = (lane >> 4) << 3;             // 0 or 8 (k offset)
    const int brow_l = ((lane >> 4) << 3) | (lane & 7);  // n offset within 16
    const int bcol_l = ((lane >> 3) & 1) << 3;       // 0 or 8 (k offset)

    auto issue = [&](int c, int buf) {
        const __half* ap = A + arowoff + akb + c * 32 + sseg * 8;
        const __half* bp = g_Bc + gbase + (size_t)srow * 256 + c * 32 + sseg * 8;
        const uint32_t da = sabase + (uint32_t)((buf * 128 + srow) * 80 + sseg * 16);
        const uint32_t db = sbbase + (uint32_t)((buf * 128 + srow) * 80 + sseg * 16);
        cp16(da,      ap);
        cp16(da + 16, (const char*)ap + 16);
        cp16(db,      bp);
        cp16(db + 16, (const char*)bp + 16);
        asm volatile("cp.async.commit_group;" ::: "memory");
    };

    issue(0, 0);
    for (int ci = 0; ci < nch; ci++) {
        asm volatile("cp.async.wait_group 0;" ::: "memory");
        __syncthreads();   // all copies visible; prior chunk's reads complete
        if (ci + 1 < nch) issue(ci + 1, (ci + 1) & 1);

        const int buf = ci & 1;
        const uint32_t abase0 = sabase +
            (uint32_t)((buf * 128 + wm * 64 + arow_l) * 80 + acol_l * 2);
        const uint32_t bbase0 = sbbase +
            (uint32_t)((buf * 128 + wn * 32 + brow_l) * 80 + bcol_l * 2);

#pragma unroll
        for (int ks = 0; ks < 2; ks++) {
            const uint32_t kb = (uint32_t)(ks * 32);   // k0*2 bytes
            uint32_t a[4][4], b[4][2];
#pragma unroll
            for (int i = 0; i < 4; i++)
                asm volatile(
                    "ldmatrix.sync.aligned.m8n8.x4.shared.b16 {%0,%1,%2,%3}, [%4];"
                    : "=r"(a[i][0]), "=r"(a[i][1]), "=r"(a[i][2]), "=r"(a[i][3])
                    : "r"(abase0 + kb + i * 1280));
#pragma unroll
            for (int jp = 0; jp < 2; jp++)
                asm volatile(
                    "ldmatrix.sync.aligned.m8n8.x4.shared.b16 {%0,%1,%2,%3}, [%4];"
                    : "=r"(b[2 * jp][0]), "=r"(b[2 * jp][1]),
                      "=r"(b[2 * jp + 1][0]), "=r"(b[2 * jp + 1][1])
                    : "r"(bbase0 + kb + jp * 1280));
#pragma unroll
            for (int i = 0; i < 4; i++)
#pragma unroll
                for (int j = 0; j < 4; j++)
                    asm volatile(
                        "mma.sync.aligned.m16n8k16.row.col.f32.f16.f16.f32 "
                        "{%0,%1,%2,%3}, {%4,%5,%6,%7}, {%8,%9}, {%0,%1,%2,%3};"
                        : "+f"(acc[i][j][0]), "+f"(acc[i][j][1]),
                          "+f"(acc[i][j][2]), "+f"(acc[i][j][3])
                        : "r"(a[i][0]), "r"(a[i][1]), "r"(a[i][2]), "r"(a[i][3]),
                          "r"(b[j][0]), "r"(b[j][1]));
        }
    }

    // ---- Epilogue ----
    if (mode == 0) {
        const int gcb = slot * 128 + wn * 32;
#pragma unroll
        for (int i = 0; i < 4; i++) {
            const int lr = wm * 64 + i * 16 + grp;
            size_t r0, r1;
            if (which < 0) { r0 = (size_t)(row0 + lr) * 1664; r1 = (size_t)(row0 + lr + 8) * 1664; }
            else           { r0 = (size_t)sIdx[lr] * 1664;    r1 = (size_t)sIdx[lr + 8] * 1664;    }
#pragma unroll
            for (int j = 0; j < 4; j++) {
                const int col = gcb + j * 8 + tig * 2;
                *(__half2*)&g_gbuf[r0 + col] = __floats2half2_rn(acc[i][j][0], acc[i][j][1]);
                *(__half2*)&g_gbuf[r1 + col] = __floats2half2_rn(acc[i][j][2], acc[i][j][3]);
            }
        }
    } else {
        // Leaf: h = tanh(acc + bW[3]) -> level-7 Az h-slots (off(7) = 0).
#pragma unroll
        for (int j = 0; j < 4; j++) {
            const int col = wn * 32 + j * 8 + tig * 2;
            const float b0 = __ldg(&bW[384 + col]);
            const float b1 = __ldg(&bW[384 + col + 1]);
#pragma unroll
            for (int i = 0; i < 4; i++) {
#pragma unroll
                for (int half = 0; half < 2; half++) {
                    const int lr = row0 + wm * 64 + i * 16 + grp + half * 8;
                    const float h0 = tanh_(acc[i][j][half * 2 + 0] + b0);
                    const float h1 = tanh_(acc[i][j][half * 2 + 1] + b1);
                    const int bb = lr >> 8, nn = lr & 255;
                    const int prow = (bb << 7) + (nn >> 1);
                    const int side = nn & 1;
                    const size_t o = (size_t)prow * 384 + 128 + side * 128 + col;
                    *(__half2*)&g_Az[o] = __floats2half2_rn(h0, h1);
                }
            }
        }
    }
}

// ---------------------------------------------------------------------------
// Pointwise LSTM cell update for level l. czero: children are leaves (c = 0).
// ---------------------------------------------------------------------------
__global__ __launch_bounds__(128)
void pointwise_kernel(int l, int cin, int czero, int poff,
                      const int* __restrict__ arity,
                      const float* __restrict__ bW,
                      const float* __restrict__ bUbin,
                      const float* __restrict__ bUun,
                      float* __restrict__ out)
{
    const int row = blockIdx.x;
    const int col = threadIdx.x;
    const int b = row >> l;
    const int n = row - (b << l);
    const int ar = __ldg(&arity[b * NARITY + ((1 << l) - 1) + n]);
    const size_t childrow = ((size_t)b << (l + 1)) + 2 * n;
    const float cl = czero ? 0.f : g_cbuf[cin][childrow * 128 + col];
    const float cr = czero ? 0.f : g_cbuf[cin][(childrow + 1) * 128 + col];
    const __half* gb = g_gbuf + (size_t)row * 1664;

    const float wx0 = __half2float(gb[0 * 128 + col]) + __ldg(&bW[0 * 128 + col]);
    const float wx1 = __half2float(gb[1 * 128 + col]) + __ldg(&bW[1 * 128 + col]);
    const float wx2 = __half2float(gb[2 * 128 + col]) + __ldg(&bW[2 * 128 + col]);
    const float wx3 = __half2float(gb[3 * 128 + col]) + __ldg(&bW[3 * 128 + col]);

    float hv, cv;
    if (ar == 1) {
        const float ig = sigmoid_(wx0 + __half2float(gb[4 * 128 + col]) + __ldg(&bUbin[0 * 128 + col]));
        const float fl = sigmoid_(wx1 + __half2float(gb[5 * 128 + col]) + __ldg(&bUbin[1 * 128 + col]));
        const float fr = sigmoid_(wx1 + __half2float(gb[6 * 128 + col]) + __ldg(&bUbin[2 * 128 + col]));
        const float og = sigmoid_(wx2 + __half2float(gb[7 * 128 + col]) + __ldg(&bUbin[3 * 128 + col]));
        const float ug = tanh_   (wx3 + __half2float(gb[8 * 128 + col]) + __ldg(&bUbin[4 * 128 + col]));
        cv = ig * ug + fl * cl + fr * cr;
        hv = og * tanh_(cv);
    } else {
        const float ig = sigmoid_(wx0 + __half2float(gb[ 9 * 128 + col]) + __ldg(&bUun[0 * 128 + col]));
        const float fg = sigmoid_(wx1 + __half2float(gb[10 * 128 + col]) + __ldg(&bUun[1 * 128 + col]));
        const float og = sigmoid_(wx2 + __half2float(gb[11 * 128 + col]) + __ldg(&bUun[2 * 128 + col]));
        const float ug = tanh_   (wx3 + __half2float(gb[12 * 128 + col]) + __ldg(&bUun[3 * 128 + col]));
        cv = ig * ug + fg * cl;
        hv = og * tanh_(cv);
    }

    g_cbuf[1 - cin][(size_t)row * 128 + col] = cv;

    if (l == 0) {
        out[row * 128 + col] = hv;
        out[BATCH * HDIM + row * 128 + col] = cv;
    } else {
        const int prow = (b << (l - 1)) + (n >> 1);
        const int side = n & 1;
        g_Az[(size_t)(poff + prow) * 384 + 128 + side * 128 + col] =
            __float2half_rn(hv);
    }
}

// ---------------------------------------------------------------------------
extern "C" void kernel_launch(void* const* d_in, const int* in_sizes, int n_in,
                              void* d_out, int out_size)
{
    const int*   tokens = (const int*)  d_in[0];
    const int*   arity  = (const int*)  d_in[1];
    const float* emb    = (const float*)d_in[2];
    const float* W      = (const float*)d_in[3];
    const float* bW     = (const float*)d_in[4];
    const float* Ubin   = (const float*)d_in[5];
    const float* bUbin  = (const float*)d_in[6];
    const float* Uun    = (const float*)d_in[7];
    const float* bUun   = (const float*)d_in[8];
    float* out = (float*)d_out;

    prep_B_kernel<<<(13 * 128 * 256 + 255) / 256, 256>>>(W, Ubin, Uun);
    stage_all_kernel<<<(LEAF_ELEMS + AZROWS * 128) / 256, 256>>>(tokens, emb);
    classify_all_kernel<<<AZROWS / 256, 256>>>(arity);

    // Leaf GEMM (gate 3 = W[3]) -> level-7 Az h-slots
    {
        dim3 grid(1, 65536 / 128);
        gemm_kernel<<<grid, 256>>>(1, 7, 0, bW);
    }

    // Levels 7..0: one fused GEMM + one pointwise per level
    for (int l = 7; l >= 0; l--) {
        const int rows = BATCH << l;
        const int off  = 256 * (256 - (2 << l));
        const int poff = (l > 0) ? 256 * (256 - (1 << l)) : 0;
        const int cin  = (7 - l) & 1;
        dim3 ggrid(13, rows / 128);
        gemm_kernel<<<ggrid, 256>>>(0, l, off, bW);
        pointwise_kernel<<<rows, 128>>>(l, cin, (l == 7) ? 1 : 0, poff,
                                        arity, bW, bUbin, bUun,
                                        (l == 0) ? out : nullptr);
    }
}